// round 1
// baseline (speedup 1.0000x reference)
#include <cuda_runtime.h>
#include <math.h>

#define NPTS 131072   // B*N
#define NB   65536    // N (points per batch)
#define KNN  32
#define FD   64

// Scratch (no allocations allowed)
__device__ float g_x1[NPTS * 16];   // 8 MB   lrelu(feat @ Wi^T)
__device__ float g_x2[NPTS * 32];   // 16 MB  [g1 | f1]
__device__ float g_x3[NPTS * 64];   // 32 MB  [g2 | f2]

__device__ __forceinline__ float lrelu(float x) { return fmaxf(x, 0.2f * x); }

// ---------------------------------------------------------------------------
// K1: x1 = lrelu(features @ w_init^T + b_init)   (NPTS, 16)
// Block: 256 threads = 16 points x 16 dims
// ---------------------------------------------------------------------------
__global__ __launch_bounds__(256) void k_init(
    const float* __restrict__ feat, const float* __restrict__ w,
    const float* __restrict__ b)
{
    __shared__ float4 sf4[256];          // 16 points x 64 feats
    __shared__ float  swt[64 * 16];      // transposed w_init
    __shared__ float  sb[16];
    const float* sf = (const float*)sf4;

    int tid = threadIdx.x;
    int fb  = blockIdx.x * 16;           // first point of this block

    // features rows are contiguous: 16 rows x 64 floats = 256 float4
    const float4* f4 = (const float4*)feat + (size_t)fb * 16;
    sf4[tid] = f4[tid];

#pragma unroll
    for (int e = tid; e < 1024; e += 256) {
        int d = e >> 6, i = e & 63;
        swt[i * 16 + d] = w[e];
    }
    if (tid < 16) sb[tid] = b[tid];
    __syncthreads();

    int p = tid >> 4, d = tid & 15;
    float acc = sb[d];
#pragma unroll
    for (int i = 0; i < 64; i++)
        acc = fmaf(sf[p * 64 + i], swt[i * 16 + d], acc);

    g_x1[(size_t)fb * 16 + tid] = lrelu(acc);   // coalesced
}

// ---------------------------------------------------------------------------
// K2: fused geo-MLPs of lfa1 + lfa2 (shared geometry) + x1 gather-mean.
//   g1[d] = mean_k lrelu(geo_k . w1[d] + b1[d])   d<16   -> g_x2[r][0:16]
//   f1[d] = mean_k x1[nbr_k][d]                   d<16   -> g_x2[r][16:32]
//   g2[d] = mean_k lrelu(geo_k . w2[d] + b2[d])   d<32   -> g_x3[r][0:32]
// One warp per point. Geo staged in SMEM (k=32 == warp).
// ---------------------------------------------------------------------------
__global__ __launch_bounds__(256) void k_lfa_geo(
    const float* __restrict__ pts, const int* __restrict__ idx,
    const float* __restrict__ w1, const float* __restrict__ b1,
    const float* __restrict__ w2, const float* __restrict__ b2)
{
    __shared__ float4 sgeo[8][32];
    __shared__ int    sidx[8][32];

    int lane = threadIdx.x & 31;
    int wid  = threadIdx.x >> 5;
    int r    = blockIdx.x * 8 + wid;
    int base = (r >= NB) ? NB : 0;       // batch row base

    // neighbor index (coalesced)
    int ij = idx[(size_t)r * KNN + lane];
    sidx[wid][lane] = ij;

    // center point (uniform address -> broadcast)
    float cx = pts[(size_t)r * 3 + 0];
    float cy = pts[(size_t)r * 3 + 1];
    float cz = pts[(size_t)r * 3 + 2];

    // neighbor point (scattered, L2-resident: points total 1.5 MB)
    size_t gr = (size_t)(base + ij) * 3;
    float px = pts[gr + 0], py = pts[gr + 1], pz = pts[gr + 2];

    float rx = cx - px, ry = cy - py, rz = cz - pz;
    float dist = sqrtf(fmaf(rx, rx, fmaf(ry, ry, rz * rz)));
    sgeo[wid][lane] = make_float4(rx, ry, rz, dist);

    // per-lane weight rows (L1-resident after first block)
    float4 w2r = ((const float4*)w2)[lane];
    float  b2d = b2[lane];
    float4 w1r = ((const float4*)w1)[lane & 15];
    float  b1d = b1[lane & 15];

    __syncwarp();

    float ag2 = 0.f, ag1 = 0.f, af1 = 0.f;
    int half = lane >> 4;     // 0 for lanes 0-15, 1 for 16-31
    int dlo  = lane & 15;

#pragma unroll
    for (int jj = 0; jj < 32; jj += 2) {
        // ---- g2: all lanes, both neighbors ----
        float4 gA = sgeo[wid][jj];
        float4 gB = sgeo[wid][jj + 1];
        float sA = fmaf(gA.x, w2r.x, fmaf(gA.y, w2r.y,
                   fmaf(gA.z, w2r.z, fmaf(gA.w, w2r.w, b2d))));
        ag2 += lrelu(sA);
        float sB = fmaf(gB.x, w2r.x, fmaf(gB.y, w2r.y,
                   fmaf(gB.z, w2r.z, fmaf(gB.w, w2r.w, b2d))));
        ag2 += lrelu(sB);

        // ---- g1 + f1: lanes 0-15 take neighbor jj, lanes 16-31 take jj+1 ----
        int jn = jj + half;
        float4 gC = sgeo[wid][jn];
        float sC = fmaf(gC.x, w1r.x, fmaf(gC.y, w1r.y,
                   fmaf(gC.z, w1r.z, fmaf(gC.w, w1r.w, b1d))));
        ag1 += lrelu(sC);

        int nr = sidx[wid][jn];
        af1 += g_x1[(size_t)(base + nr) * 16 + dlo];  // two 64B segments/warp
    }

    // fold odd-neighbor partials (lanes 16-31) into lanes 0-15
    ag1 += __shfl_down_sync(0xffffffffu, ag1, 16);
    af1 += __shfl_down_sync(0xffffffffu, af1, 16);

    const float inv = 1.0f / 32.0f;
    g_x3[(size_t)r * 64 + lane] = ag2 * inv;          // g2 half of x3 (coalesced)
    if (lane < 16) {
        g_x2[(size_t)r * 32 + lane]      = ag1 * inv;
        g_x2[(size_t)r * 32 + 16 + lane] = af1 * inv;
    }
}

// ---------------------------------------------------------------------------
// K3a: f2[d] = mean_k x2[nbr_k][d]  (32 dims)  -> g_x3[r][32:64]
// One warp per point; 32 independent 128B gathers per point (high MLP).
// ---------------------------------------------------------------------------
__global__ __launch_bounds__(256) void k_gather2(const int* __restrict__ idx)
{
    __shared__ int sidx[8][32];
    int lane = threadIdx.x & 31;
    int wid  = threadIdx.x >> 5;
    int r    = blockIdx.x * 8 + wid;
    int base = (r >= NB) ? NB : 0;

    sidx[wid][lane] = idx[(size_t)r * KNN + lane];
    __syncwarp();

    float acc = 0.f;
#pragma unroll
    for (int j = 0; j < 32; j++) {
        int nr = sidx[wid][j];
        acc += g_x2[(size_t)(base + nr) * 32 + lane];  // coalesced 128B
    }
    g_x3[(size_t)r * 64 + 32 + lane] = acc * (1.0f / 32.0f);
}

// ---------------------------------------------------------------------------
// K3b: out = lrelu(x3 @ wf^T + bf) + lrelu(feat @ wr^T + br)
// Tile: 128 points x 32 outs per block (grid.y = out-half), 128 threads,
// thread tile 8 points x 4 outs (register-blocked, FMA-bound).
// Two phases reuse the same SMEM x-tile (x3, then feat).
// ---------------------------------------------------------------------------
__global__ __launch_bounds__(128) void k_final(
    const float* __restrict__ feat,
    const float* __restrict__ wf, const float* __restrict__ bf,
    const float* __restrict__ wr, const float* __restrict__ br,
    float* __restrict__ out)
{
    __shared__ float4 sx4[128 * 17];                 // 128 pts x 64 f, padded (17 f4/row)
    __shared__ __align__(16) float sw[64 * 36];      // w^T, padded 36 floats/k-row
    __shared__ float sb1[32], sb2[32];

    int tid   = threadIdx.x;
    int dhalf = blockIdx.y;                          // 0: outs 0-31, 1: outs 32-63
    int r0    = blockIdx.x * 128;
    int c     = tid & 7;                             // out group: d_local = c*4
    int rw    = tid >> 3;                            // point group: p = rw + 16*i

    if (tid < 32) {
        sb1[tid] = bf[dhalf * 32 + tid];
        sb2[tid] = br[dhalf * 32 + tid];
    }

    float acc[8][4];
    float po[8][4];

    // ---------------- phase A: x3 @ wf^T ----------------
    {
        const float4* src = (const float4*)g_x3 + (size_t)r0 * 16;
#pragma unroll
        for (int e = tid; e < 2048; e += 128) {
            int p = e >> 4, k4 = e & 15;
            sx4[p * 17 + k4] = src[e];
        }
#pragma unroll
        for (int e = tid; e < 2048; e += 128) {
            int drow = e >> 6, k = e & 63;
            sw[k * 36 + drow] = wf[(size_t)(dhalf * 32 + drow) * 64 + k];
        }
    }
    __syncthreads();

#pragma unroll
    for (int i = 0; i < 8; i++)
#pragma unroll
        for (int j = 0; j < 4; j++) acc[i][j] = 0.f;

#pragma unroll
    for (int k4 = 0; k4 < 16; k4++) {
        float4 wv[4];
#pragma unroll
        for (int kk = 0; kk < 4; kk++)
            wv[kk] = *((const float4*)(sw + (k4 * 4 + kk) * 36) + c);
        float4 xv[8];
#pragma unroll
        for (int i = 0; i < 8; i++)
            xv[i] = sx4[(rw + 16 * i) * 17 + k4];
#pragma unroll
        for (int i = 0; i < 8; i++) {
            float x0 = xv[i].x, x1 = xv[i].y, x2 = xv[i].z, x3 = xv[i].w;
#pragma unroll
            for (int j = 0; j < 4; j++) {
                float* wj0 = &wv[0].x;
                acc[i][j] = fmaf(x0, (&wv[0].x)[j], acc[i][j]);
                acc[i][j] = fmaf(x1, (&wv[1].x)[j], acc[i][j]);
                acc[i][j] = fmaf(x2, (&wv[2].x)[j], acc[i][j]);
                acc[i][j] = fmaf(x3, (&wv[3].x)[j], acc[i][j]);
                (void)wj0;
            }
        }
    }

#pragma unroll
    for (int i = 0; i < 8; i++)
#pragma unroll
        for (int j = 0; j < 4; j++)
            po[i][j] = lrelu(acc[i][j] + sb1[c * 4 + j]);

    __syncthreads();   // everyone done reading phase-A tiles

    // ---------------- phase B: feat @ wr^T ----------------
    {
        const float4* src = (const float4*)feat + (size_t)r0 * 16;
#pragma unroll
        for (int e = tid; e < 2048; e += 128) {
            int p = e >> 4, k4 = e & 15;
            sx4[p * 17 + k4] = src[e];
        }
#pragma unroll
        for (int e = tid; e < 2048; e += 128) {
            int drow = e >> 6, k = e & 63;
            sw[k * 36 + drow] = wr[(size_t)(dhalf * 32 + drow) * 64 + k];
        }
    }
    __syncthreads();

#pragma unroll
    for (int i = 0; i < 8; i++)
#pragma unroll
        for (int j = 0; j < 4; j++) acc[i][j] = 0.f;

#pragma unroll
    for (int k4 = 0; k4 < 16; k4++) {
        float4 wv[4];
#pragma unroll
        for (int kk = 0; kk < 4; kk++)
            wv[kk] = *((const float4*)(sw + (k4 * 4 + kk) * 36) + c);
        float4 xv[8];
#pragma unroll
        for (int i = 0; i < 8; i++)
            xv[i] = sx4[(rw + 16 * i) * 17 + k4];
#pragma unroll
        for (int i = 0; i < 8; i++) {
            float x0 = xv[i].x, x1 = xv[i].y, x2 = xv[i].z, x3 = xv[i].w;
#pragma unroll
            for (int j = 0; j < 4; j++) {
                acc[i][j] = fmaf(x0, (&wv[0].x)[j], acc[i][j]);
                acc[i][j] = fmaf(x1, (&wv[1].x)[j], acc[i][j]);
                acc[i][j] = fmaf(x2, (&wv[2].x)[j], acc[i][j]);
                acc[i][j] = fmaf(x3, (&wv[3].x)[j], acc[i][j]);
            }
        }
    }

    // combine + store (float4 per point)
    float4* out4 = (float4*)out;
#pragma unroll
    for (int i = 0; i < 8; i++) {
        int p = rw + 16 * i;
        float4 v;
        v.x = po[i][0] + lrelu(acc[i][0] + sb2[c * 4 + 0]);
        v.y = po[i][1] + lrelu(acc[i][1] + sb2[c * 4 + 1]);
        v.z = po[i][2] + lrelu(acc[i][2] + sb2[c * 4 + 2]);
        v.w = po[i][3] + lrelu(acc[i][3] + sb2[c * 4 + 3]);
        out4[(size_t)(r0 + p) * 16 + dhalf * 8 + c] = v;
    }
}

// ---------------------------------------------------------------------------
extern "C" void kernel_launch(void* const* d_in, const int* in_sizes, int n_in,
                              void* d_out, int out_size)
{
    const float* points  = (const float*)d_in[0];
    const float* feats   = (const float*)d_in[1];
    const int*   idx     = (const int*)d_in[2];
    const float* w_init  = (const float*)d_in[3];
    const float* b_init  = (const float*)d_in[4];
    const float* w_lfa1  = (const float*)d_in[5];
    const float* b_lfa1  = (const float*)d_in[6];
    const float* w_lfa2  = (const float*)d_in[7];
    const float* b_lfa2  = (const float*)d_in[8];
    const float* w_final = (const float*)d_in[9];
    const float* b_final = (const float*)d_in[10];
    const float* w_res   = (const float*)d_in[11];
    const float* b_res   = (const float*)d_in[12];
    float* out = (float*)d_out;

    k_init<<<NPTS / 16, 256>>>(feats, w_init, b_init);
    k_lfa_geo<<<NPTS / 8, 256>>>(points, idx, w_lfa1, b_lfa1, w_lfa2, b_lfa2);
    k_gather2<<<NPTS / 8, 256>>>(idx);
    k_final<<<dim3(NPTS / 128, 2), 128>>>(feats, w_final, b_final,
                                          w_res, b_res, out);
}

// round 2
// speedup vs baseline: 1.1780x; 1.1780x over previous
#include <cuda_runtime.h>
#include <math.h>

#define NPTS 131072   // B*N
#define NB   65536    // N (points per batch)
#define KNN  32
#define FD   64

typedef unsigned long long u64;

// Scratch (no allocations allowed)
__device__ float g_x1[NPTS * 16];   // 8 MB   lrelu(feat @ Wi^T)
__device__ float g_x2[NPTS * 32];   // 16 MB  [g1 | f1]
__device__ float g_x3[NPTS * 64];   // 32 MB  [g2 | f2]

__device__ __forceinline__ float lrelu(float x) { return fmaxf(x, 0.2f * x); }

// ---- packed f32x2 helpers (sm_103a FFMA2 path) ----
__device__ __forceinline__ u64 fma2(u64 a, u64 b, u64 c) {
    u64 r;
    asm("fma.rn.f32x2 %0, %1, %2, %3;" : "=l"(r) : "l"(a), "l"(b), "l"(c));
    return r;
}
__device__ __forceinline__ u64 pk2(float x, float y) {
    u64 r;
    asm("mov.b64 %0, {%1, %2};" : "=l"(r) : "f"(x), "f"(y));
    return r;
}
__device__ __forceinline__ float2 up2(u64 a) {
    float2 v;
    asm("mov.b64 {%0, %1}, %2;" : "=f"(v.x), "=f"(v.y) : "l"(a));
    return v;
}
#define C06_2 0x3F19999A3F19999AULL   // {0.6f, 0.6f}
#define C04_2 0x3ECCCCCD3ECCCCCDULL   // {0.4f, 0.4f}
#define ABSM  0x7FFFFFFF7FFFFFFFULL

// packed lrelu accumulate: acc += lrelu2(s)  where lrelu(x)=0.6x+0.4|x|
__device__ __forceinline__ u64 lrelu_acc2(u64 s, u64 acc) {
    acc = fma2(s, C06_2, acc);
    acc = fma2(s & ABSM, C04_2, acc);
    return acc;
}

// ---------------------------------------------------------------------------
// K1: x1 = lrelu(features @ w_init^T + b_init)   (NPTS, 16)
// ---------------------------------------------------------------------------
__global__ __launch_bounds__(256) void k_init(
    const float* __restrict__ feat, const float* __restrict__ w,
    const float* __restrict__ b)
{
    __shared__ float4 sf4[256];          // 16 points x 64 feats
    __shared__ float  swt[64 * 16];      // transposed w_init
    __shared__ float  sb[16];
    const float* sf = (const float*)sf4;

    int tid = threadIdx.x;
    int fb  = blockIdx.x * 16;

    const float4* f4 = (const float4*)feat + (size_t)fb * 16;
    sf4[tid] = f4[tid];

#pragma unroll
    for (int e = tid; e < 1024; e += 256) {
        int d = e >> 6, i = e & 63;
        swt[i * 16 + d] = w[e];
    }
    if (tid < 16) sb[tid] = b[tid];
    __syncthreads();

    int p = tid >> 4, d = tid & 15;
    float acc = sb[d];
#pragma unroll
    for (int i = 0; i < 64; i++)
        acc = fmaf(sf[p * 64 + i], swt[i * 16 + d], acc);

    g_x1[(size_t)fb * 16 + tid] = lrelu(acc);
}

// ---------------------------------------------------------------------------
// K2: fused geo-MLPs of lfa1 + lfa2 (shared geometry) + x1 gather-mean.
// One warp per point. Geo staged SoA in SMEM; packed f32x2 over neighbor pairs.
//   g2[d]  d<32  -> g_x3[r][0:32]
//   g1[d]  d<16  -> g_x2[r][0:16]
//   f1[d]  d<16  -> g_x2[r][16:32]
// ---------------------------------------------------------------------------
__global__ __launch_bounds__(256) void k_lfa_geo(
    const float* __restrict__ pts, const int* __restrict__ idx,
    const float* __restrict__ w1, const float* __restrict__ b1,
    const float* __restrict__ w2, const float* __restrict__ b2)
{
    __shared__ __align__(16) float sgx[8][32];
    __shared__ __align__(16) float sgy[8][32];
    __shared__ __align__(16) float sgz[8][32];
    __shared__ __align__(16) float sgd[8][32];
    __shared__ int sidx[8][32];

    int lane = threadIdx.x & 31;
    int wid  = threadIdx.x >> 5;
    int r    = blockIdx.x * 8 + wid;
    int base = (r >= NB) ? NB : 0;       // batch row base

    int ij = idx[(size_t)r * KNN + lane];
    sidx[wid][lane] = ij;

    float cx = pts[(size_t)r * 3 + 0];
    float cy = pts[(size_t)r * 3 + 1];
    float cz = pts[(size_t)r * 3 + 2];

    size_t gr = (size_t)(base + ij) * 3;
    float px = pts[gr + 0], py = pts[gr + 1], pz = pts[gr + 2];

    float rx = cx - px, ry = cy - py, rz = cz - pz;
    float dist = sqrtf(fmaf(rx, rx, fmaf(ry, ry, rz * rz)));
    sgx[wid][lane] = rx;
    sgy[wid][lane] = ry;
    sgz[wid][lane] = rz;
    sgd[wid][lane] = dist;

    // per-lane weight rows, packed {w,w}
    float4 w2r = ((const float4*)w2)[lane];
    u64 w2xx = pk2(w2r.x, w2r.x), w2yy = pk2(w2r.y, w2r.y);
    u64 w2zz = pk2(w2r.z, w2r.z), w2ww = pk2(w2r.w, w2r.w);
    u64 bias2 = pk2(b2[lane], b2[lane]);

    int dlo = lane & 15;
    int h   = lane >> 4;
    float4 w1r = ((const float4*)w1)[dlo];
    u64 w1xx = pk2(w1r.x, w1r.x), w1yy = pk2(w1r.y, w1r.y);
    u64 w1zz = pk2(w1r.z, w1r.z), w1ww = pk2(w1r.w, w1r.w);
    u64 bias1 = pk2(b1[dlo], b1[dlo]);

    __syncwarp();

    u64 ag2 = 0, ag1 = 0;
    float af1 = 0.f;

#pragma unroll
    for (int it = 0; it < 8; it++) {
        int j0 = it * 4;
        // LDS.128 broadcast: two packed neighbor-pairs per component
        ulonglong2 gx = *(const ulonglong2*)&sgx[wid][j0];
        ulonglong2 gy = *(const ulonglong2*)&sgy[wid][j0];
        ulonglong2 gz = *(const ulonglong2*)&sgz[wid][j0];
        ulonglong2 gd = *(const ulonglong2*)&sgd[wid][j0];

        // ---- g2: all 32 lanes (d = lane), both pairs ----
        u64 s0 = fma2(gx.x, w2xx, bias2);
        s0 = fma2(gy.x, w2yy, s0);
        s0 = fma2(gz.x, w2zz, s0);
        s0 = fma2(gd.x, w2ww, s0);
        ag2 = lrelu_acc2(s0, ag2);

        u64 s1 = fma2(gx.y, w2xx, bias2);
        s1 = fma2(gy.y, w2yy, s1);
        s1 = fma2(gz.y, w2zz, s1);
        s1 = fma2(gd.y, w2ww, s1);
        ag2 = lrelu_acc2(s1, ag2);

        // ---- g1: lanes<16 take pair0, lanes>=16 take pair1 (dims dlo) ----
        u64 qx = h ? gx.y : gx.x;
        u64 qy = h ? gy.y : gy.x;
        u64 qz = h ? gz.y : gz.x;
        u64 qd = h ? gd.y : gd.x;
        u64 t = fma2(qx, w1xx, bias1);
        t = fma2(qy, w1yy, t);
        t = fma2(qz, w1zz, t);
        t = fma2(qd, w1ww, t);
        ag1 = lrelu_acc2(t, ag1);

        // ---- f1 gather: lanes<16 rows j0,j0+1; lanes>=16 rows j0+2,j0+3 ----
        int jb = j0 + 2 * h;
        int n0 = sidx[wid][jb];
        int n1 = sidx[wid][jb + 1];
        af1 += g_x1[(size_t)(base + n0) * 16 + dlo];
        af1 += g_x1[(size_t)(base + n1) * 16 + dlo];
    }

    const float inv = 1.0f / 32.0f;

    float2 a2 = up2(ag2);
    g_x3[(size_t)r * 64 + lane] = (a2.x + a2.y) * inv;

    // fold lane-halves for g1 / f1
    u64 ag1o = __shfl_down_sync(0xffffffffu, ag1, 16);
    float af1o = __shfl_down_sync(0xffffffffu, af1, 16);
    if (lane < 16) {
        float2 a1  = up2(ag1);
        float2 a1o = up2(ag1o);
        g_x2[(size_t)r * 32 + lane]      = (a1.x + a1.y + a1o.x + a1o.y) * inv;
        g_x2[(size_t)r * 32 + 16 + lane] = (af1 + af1o) * inv;
    }
}

// ---------------------------------------------------------------------------
// K3a: f2[d] = mean_k x2[nbr_k][d]  (32 dims)  -> g_x3[r][32:64]
// ---------------------------------------------------------------------------
__global__ __launch_bounds__(256) void k_gather2(const int* __restrict__ idx)
{
    __shared__ int sidx[8][32];
    int lane = threadIdx.x & 31;
    int wid  = threadIdx.x >> 5;
    int r    = blockIdx.x * 8 + wid;
    int base = (r >= NB) ? NB : 0;

    sidx[wid][lane] = idx[(size_t)r * KNN + lane];
    __syncwarp();

    float acc = 0.f;
#pragma unroll
    for (int j = 0; j < 32; j++) {
        int nr = sidx[wid][j];
        acc += g_x2[(size_t)(base + nr) * 32 + lane];  // coalesced 128B
    }
    g_x3[(size_t)r * 64 + 32 + lane] = acc * (1.0f / 32.0f);
}

// ---------------------------------------------------------------------------
// K3b: out = lrelu(x3 @ wf^T + bf) + lrelu(feat @ wr^T + br)
// SMEM-free: warp-broadcast LDG for x-rows (4 distinct addr) and w-rows
// (8 distinct addr, L1-resident). Packed f32x2 FMA along k (k-contiguous in
// both operands -> zero packing movs). Thread tile: 8 points x 4 outs.
// ---------------------------------------------------------------------------
__global__ __launch_bounds__(128) void k_final(
    const float* __restrict__ feat,
    const float* __restrict__ wf, const float* __restrict__ bf,
    const float* __restrict__ wr, const float* __restrict__ br,
    float* __restrict__ out)
{
    int tid   = threadIdx.x;
    int dhalf = blockIdx.y;                  // 0: outs 0-31, 1: outs 32-63
    int r0    = blockIdx.x * 128;
    int c     = tid & 7;
    int rw    = tid >> 3;                    // point p = rw + 16*i
    int dbase = dhalf * 32 + c * 4;

    u64 acc[8][4];
    float po[8][4];

    // ---------------- phase A: x3 @ wf^T ----------------
#pragma unroll
    for (int i = 0; i < 8; i++)
#pragma unroll
        for (int j = 0; j < 4; j++) acc[i][j] = 0ull;

    const float* xbase = g_x3 + (size_t)(r0 + rw) * 64;
#pragma unroll
    for (int k4 = 0; k4 < 16; k4++) {
        ulonglong2 wv[4];
#pragma unroll
        for (int j = 0; j < 4; j++)
            wv[j] = *(const ulonglong2*)(wf + (size_t)(dbase + j) * 64 + k4 * 4);
#pragma unroll
        for (int i = 0; i < 8; i++) {
            ulonglong2 xv = *(const ulonglong2*)(xbase + (size_t)i * 1024 + k4 * 4);
#pragma unroll
            for (int j = 0; j < 4; j++) {
                acc[i][j] = fma2(xv.x, wv[j].x, acc[i][j]);
                acc[i][j] = fma2(xv.y, wv[j].y, acc[i][j]);
            }
        }
    }

    {
        float4 bv = *(const float4*)(bf + dbase);
#pragma unroll
        for (int i = 0; i < 8; i++) {
#pragma unroll
            for (int j = 0; j < 4; j++) {
                float2 v = up2(acc[i][j]);
                float s = v.x + v.y + (&bv.x)[j];
                po[i][j] = lrelu(s);
            }
        }
    }

    // ---------------- phase B: feat @ wr^T ----------------
#pragma unroll
    for (int i = 0; i < 8; i++)
#pragma unroll
        for (int j = 0; j < 4; j++) acc[i][j] = 0ull;

    const float* fbase = feat + (size_t)(r0 + rw) * 64;
#pragma unroll
    for (int k4 = 0; k4 < 16; k4++) {
        ulonglong2 wv[4];
#pragma unroll
        for (int j = 0; j < 4; j++)
            wv[j] = *(const ulonglong2*)(wr + (size_t)(dbase + j) * 64 + k4 * 4);
#pragma unroll
        for (int i = 0; i < 8; i++) {
            ulonglong2 xv = *(const ulonglong2*)(fbase + (size_t)i * 1024 + k4 * 4);
#pragma unroll
            for (int j = 0; j < 4; j++) {
                acc[i][j] = fma2(xv.x, wv[j].x, acc[i][j]);
                acc[i][j] = fma2(xv.y, wv[j].y, acc[i][j]);
            }
        }
    }

    // combine + store (float4 per point)
    float4 bv2 = *(const float4*)(br + dbase);
    float4* out4 = (float4*)out;
#pragma unroll
    for (int i = 0; i < 8; i++) {
        int p = rw + 16 * i;
        float4 v;
#pragma unroll
        for (int j = 0; j < 4; j++) {
            float2 w2 = up2(acc[i][j]);
            float s = w2.x + w2.y + (&bv2.x)[j];
            (&v.x)[j] = po[i][j] + lrelu(s);
        }
        out4[(size_t)(r0 + p) * 16 + dhalf * 8 + c] = v;
    }
}

// ---------------------------------------------------------------------------
extern "C" void kernel_launch(void* const* d_in, const int* in_sizes, int n_in,
                              void* d_out, int out_size)
{
    const float* points  = (const float*)d_in[0];
    const float* feats   = (const float*)d_in[1];
    const int*   idx     = (const int*)d_in[2];
    const float* w_init  = (const float*)d_in[3];
    const float* b_init  = (const float*)d_in[4];
    const float* w_lfa1  = (const float*)d_in[5];
    const float* b_lfa1  = (const float*)d_in[6];
    const float* w_lfa2  = (const float*)d_in[7];
    const float* b_lfa2  = (const float*)d_in[8];
    const float* w_final = (const float*)d_in[9];
    const float* b_final = (const float*)d_in[10];
    const float* w_res   = (const float*)d_in[11];
    const float* b_res   = (const float*)d_in[12];
    float* out = (float*)d_out;

    k_init<<<NPTS / 16, 256>>>(feats, w_init, b_init);
    k_lfa_geo<<<NPTS / 8, 256>>>(points, idx, w_lfa1, b_lfa1, w_lfa2, b_lfa2);
    k_gather2<<<NPTS / 8, 256>>>(idx);
    k_final<<<dim3(NPTS / 128, 2), 128>>>(feats, w_final, b_final,
                                          w_res, b_res, out);
}